// round 14
// baseline (speedup 1.0000x reference)
#include <cuda_runtime.h>
#include <math.h>

#define N_TOK   4096
#define H_DIM   128
#define NH      8
#define HD      16
#define FF_DIM  256
#define L_LAYER 4
#define LAT_DIM 16
#define CAP     128

// ---------------- scratch (static device globals; no runtime alloc) ----------------
__device__ __align__(256) float g_x   [N_TOK * H_DIM];
__device__ __align__(256) float g_xn  [N_TOK * H_DIM];
__device__ __align__(256) float g_qkv [N_TOK * 3 * H_DIM];
__device__ __align__(256) float g_attn[N_TOK * H_DIM];
__device__ __align__(256) float g_tmp [N_TOK * FF_DIM];
__device__ __align__(256) float g_lat [N_TOK * LAT_DIM];
__device__ __align__(256) float g_beta[N_TOK];
__device__ __align__(256) int   g_nbr [N_TOK * CAP];
__device__ __align__(256) int   g_ncnt[N_TOK];

// ---------------- neighbor list build: eta/phi inline, smem-staged ----------------
__global__ __launch_bounds__(256)
void nbr_kernel(const float* __restrict__ x_raw) {
    __shared__ float se[N_TOK];
    __shared__ float sp[N_TOK];
    const int tid = threadIdx.x;
    #pragma unroll
    for (int t = 0; t < N_TOK / 256; t++) {
        int i = tid + t * 256;
        se[i] = x_raw[i * 16 + 1] * 5.24f   + (-2.62f);
        sp[i] = x_raw[i * 16 + 2] * 6.2832f + (-3.1416f);
    }
    __syncthreads();

    const int lane = tid & 31;
    const int q    = blockIdx.x * 8 + (tid >> 5);
    const float eq = se[q], pq = sp[q];
    int cnt = 0;
    for (int k = lane; k < N_TOK; k += 32) {
        float de = eq - se[k];
        float dp = pq - sp[k];
        dp -= 6.28318530718f * rintf(dp * 0.159154943092f);
        bool hit = (de * de + dp * dp) <= 0.04f;
        unsigned mask = __ballot_sync(0xffffffffu, hit);
        if (hit) {
            int off = cnt + __popc(mask & ((1u << lane) - 1u));
            if (off < CAP) g_nbr[q * CAP + off] = k;
        }
        cnt += __popc(mask);
    }
    if (lane == 0) g_ncnt[q] = min(cnt, CAP);
}

// ---------------- tf32 tensor-core GEMM: 64x64 tile, fragment-major smem -----------
// C = A(NxK) @ W(MxK)^T + bias (+res)(relu?). 256 threads = 8 warps.
// Warp w: rows (w>>1)*16..+15, cols (w&1)*32..+31 (4 n8 tiles). mma.m16n8k8 tf32.
// Smem holds mma fragments directly: A frag = LDS.128/lane, B frag = LDS.64/lane.
#define GM 64
#define GN 64
#define GK 16

__device__ __forceinline__ unsigned f2tf32(float f) {
    unsigned u;
    asm("cvt.rna.tf32.f32 %0, %1;" : "=r"(u) : "f"(f));
    return u;
}

__global__ __launch_bounds__(256)
void gemm_mma_kernel(const float* __restrict__ A, const float* __restrict__ W,
                     const float* __restrict__ bias, const float* __restrict__ res,
                     float* __restrict__ C, int N, int M, int K, int relu) {
    // AF[buf][rowblock 0..3][kb 0..1][lane][4]  (a0,a1,a2,a3)
    // WF[buf][n8tile  0..7][kb 0..1][lane][2]  (b0,b1)
    __shared__ __align__(16) unsigned AF[2][4][2][32][4];
    __shared__ __align__(16) unsigned WF[2][8][2][32][2];

    const int tid  = threadIdx.x;
    const int row0 = blockIdx.x * GM;
    const int col0 = blockIdx.y * GN;
    const int wrp  = tid >> 5;
    const int lane = tid & 31;
    const int rb   = wrp >> 1;                // warp row-block (16 rows)
    const int ntb  = (wrp & 1) * 4;           // first n8 tile of this warp

    // staging coords: 1 float4 of A and 1 of W per thread
    const int sr = tid >> 2;                  // row/col 0..63
    const int kq = (tid & 3) << 2;            // 0,4,8,12
    const int skb  = kq >> 3;                 // k-block 0/1
    const int sidxh = ((kq & 7) >> 2);        // high idx bit source (0 or 1)

    // A staging targets
    const int arb   = sr >> 4;
    const int arr   = sr & 15;
    const int alane = (arr & 7) * 4;          // + u
    const int aidx  = (arr >> 3) | (sidxh << 1);
    // W staging targets
    const int wnt   = sr >> 3;
    const int wlane = (sr & 7) * 4;           // + u
    const int widx  = sidxh;

    float4 pa, pw;
    {
        int ga = row0 + sr;
        pa = (ga < N) ? *(const float4*)(A + (size_t)ga * K + kq) : make_float4(0,0,0,0);
        int gw = col0 + sr;
        pw = (gw < M) ? *(const float4*)(W + (size_t)gw * K + kq) : make_float4(0,0,0,0);
    }
    AF[0][arb][skb][alane + 0][aidx] = f2tf32(pa.x);
    AF[0][arb][skb][alane + 1][aidx] = f2tf32(pa.y);
    AF[0][arb][skb][alane + 2][aidx] = f2tf32(pa.z);
    AF[0][arb][skb][alane + 3][aidx] = f2tf32(pa.w);
    WF[0][wnt][skb][wlane + 0][widx] = f2tf32(pw.x);
    WF[0][wnt][skb][wlane + 1][widx] = f2tf32(pw.y);
    WF[0][wnt][skb][wlane + 2][widx] = f2tf32(pw.z);
    WF[0][wnt][skb][wlane + 3][widx] = f2tf32(pw.w);
    __syncthreads();

    float c[4][4];
    #pragma unroll
    for (int j = 0; j < 4; j++)
        #pragma unroll
        for (int i = 0; i < 4; i++) c[j][i] = 0.f;

    const int nk = K / GK;
    for (int t = 0; t < nk; t++) {
        int buf = t & 1;
        if (t + 1 < nk) {
            int koff = (t + 1) * GK + kq;
            int ga = row0 + sr;
            pa = (ga < N) ? *(const float4*)(A + (size_t)ga * K + koff) : make_float4(0,0,0,0);
            int gw = col0 + sr;
            pw = (gw < M) ? *(const float4*)(W + (size_t)gw * K + koff) : make_float4(0,0,0,0);
        }

        #pragma unroll
        for (int kb = 0; kb < 2; kb++) {
            uint4 av = *(const uint4*)&AF[buf][rb][kb][lane][0];
            #pragma unroll
            for (int j = 0; j < 4; j++) {
                uint2 bv = *(const uint2*)&WF[buf][ntb + j][kb][lane][0];
                asm("mma.sync.aligned.m16n8k8.row.col.f32.tf32.tf32.f32 "
                    "{%0,%1,%2,%3}, {%4,%5,%6,%7}, {%8,%9}, {%0,%1,%2,%3};"
                    : "+f"(c[j][0]), "+f"(c[j][1]), "+f"(c[j][2]), "+f"(c[j][3])
                    : "r"(av.x), "r"(av.y), "r"(av.z), "r"(av.w), "r"(bv.x), "r"(bv.y));
            }
        }

        if (t + 1 < nk) {
            int nb = buf ^ 1;
            AF[nb][arb][skb][alane + 0][aidx] = f2tf32(pa.x);
            AF[nb][arb][skb][alane + 1][aidx] = f2tf32(pa.y);
            AF[nb][arb][skb][alane + 2][aidx] = f2tf32(pa.z);
            AF[nb][arb][skb][alane + 3][aidx] = f2tf32(pa.w);
            WF[nb][wnt][skb][wlane + 0][widx] = f2tf32(pw.x);
            WF[nb][wnt][skb][wlane + 1][widx] = f2tf32(pw.y);
            WF[nb][wnt][skb][wlane + 2][widx] = f2tf32(pw.z);
            WF[nb][wnt][skb][wlane + 3][widx] = f2tf32(pw.w);
            __syncthreads();
        }
    }

    // epilogue: c[j][0,1] -> row r0+frow, cols 2*fcol(+1); c[j][2,3] -> row+8
    const int frow = lane >> 2;
    const int fcol = lane & 3;
    const int r0   = rb * 16;
    const int n0   = (wrp & 1) * 32;
    #pragma unroll
    for (int j = 0; j < 4; j++) {
        int gmBase = col0 + n0 + j * 8 + fcol * 2;
        #pragma unroll
        for (int half = 0; half < 2; half++) {
            int gr = row0 + r0 + frow + half * 8;
            if (gr >= N) continue;
            #pragma unroll
            for (int cc = 0; cc < 2; cc++) {
                int gm = gmBase + cc;
                if (gm >= M) continue;
                float v = c[j][half * 2 + cc] + bias[gm];
                if (res)  v += res[(size_t)gr * M + gm];
                if (relu) v = fmaxf(v, 0.f);
                C[(size_t)gr * M + gm] = v;
            }
        }
    }
}

// ---------------- LayerNorm: one warp per row, 8 rows per 256-thread block ---------
__global__ __launch_bounds__(256)
void ln_kernel(const float* __restrict__ x, const float* __restrict__ sc,
               const float* __restrict__ bi, float* __restrict__ out) {
    const int row  = blockIdx.x * 8 + (threadIdx.x >> 5);
    const int lane = threadIdx.x & 31;

    float4 v = *(const float4*)(x + (size_t)row * H_DIM + lane * 4);
    float s  = v.x + v.y + v.z + v.w;
    float s2 = v.x * v.x + v.y * v.y + v.z * v.z + v.w * v.w;
    #pragma unroll
    for (int o = 16; o; o >>= 1) {
        s  += __shfl_xor_sync(0xffffffffu, s,  o);
        s2 += __shfl_xor_sync(0xffffffffu, s2, o);
    }
    float mean = s * (1.f / 128.f);
    float var  = s2 * (1.f / 128.f) - mean * mean;
    float inv  = rsqrtf(var + 1e-5f);

    float4 sc4 = *(const float4*)(sc + lane * 4);
    float4 bi4 = *(const float4*)(bi + lane * 4);
    float4 o4;
    o4.x = (v.x - mean) * inv * sc4.x + bi4.x;
    o4.y = (v.y - mean) * inv * sc4.y + bi4.y;
    o4.z = (v.z - mean) * inv * sc4.z + bi4.z;
    o4.w = (v.w - mean) * inv * sc4.w + bi4.w;
    *(float4*)(out + (size_t)row * H_DIM + lane * 4) = o4;
}

// ---------------- sparse attention: 4 lanes per (query, head) ----------------
__global__ __launch_bounds__(256)
void attn_sparse4_kernel(const float* __restrict__ qkv, float* __restrict__ o) {
    int gid  = blockIdx.x * 256 + threadIdx.x;
    int grp  = gid >> 2;
    int lane = gid & 3;
    int q = grp >> 3;
    int h = grp & 7;

    const float* qp = qkv + (size_t)q * 384 + h * HD;
    float4 q0 = *(const float4*)(qp);
    float4 q1 = *(const float4*)(qp + 4);
    float4 q2 = *(const float4*)(qp + 8);
    float4 q3 = *(const float4*)(qp + 12);

    int cnt = g_ncnt[q];
    const int* nb = &g_nbr[q * CAP];

    float m = -1e30f, l = 0.f;
    float acc[HD];
    #pragma unroll
    for (int d = 0; d < HD; d++) acc[d] = 0.f;

    for (int j = lane; j < cnt; j += 4) {
        int kidx = nb[j];
        const float* kp = qkv + (size_t)kidx * 384 + 128 + h * HD;
        float4 k0 = *(const float4*)(kp);
        float4 k1 = *(const float4*)(kp + 4);
        float4 k2 = *(const float4*)(kp + 8);
        float4 k3 = *(const float4*)(kp + 12);
        float s = q0.x * k0.x + q0.y * k0.y + q0.z * k0.z + q0.w * k0.w
                + q1.x * k1.x + q1.y * k1.y + q1.z * k1.z + q1.w * k1.w
                + q2.x * k2.x + q2.y * k2.y + q2.z * k2.z + q2.w * k2.w
                + q3.x * k3.x + q3.y * k3.y + q3.z * k3.z + q3.w * k3.w;
        s *= 0.25f;
        float mnew = fmaxf(m, s);
        float corr = __expf(m - mnew);
        float e    = __expf(s - mnew);
        l = l * corr + e;
        const float* vp = kp + 128;
        float4 v0 = *(const float4*)(vp);
        float4 v1 = *(const float4*)(vp + 4);
        float4 v2 = *(const float4*)(vp + 8);
        float4 v3 = *(const float4*)(vp + 12);
        acc[0]  = acc[0]  * corr + e * v0.x;  acc[1]  = acc[1]  * corr + e * v0.y;
        acc[2]  = acc[2]  * corr + e * v0.z;  acc[3]  = acc[3]  * corr + e * v0.w;
        acc[4]  = acc[4]  * corr + e * v1.x;  acc[5]  = acc[5]  * corr + e * v1.y;
        acc[6]  = acc[6]  * corr + e * v1.z;  acc[7]  = acc[7]  * corr + e * v1.w;
        acc[8]  = acc[8]  * corr + e * v2.x;  acc[9]  = acc[9]  * corr + e * v2.y;
        acc[10] = acc[10] * corr + e * v2.z;  acc[11] = acc[11] * corr + e * v2.w;
        acc[12] = acc[12] * corr + e * v3.x;  acc[13] = acc[13] * corr + e * v3.y;
        acc[14] = acc[14] * corr + e * v3.z;  acc[15] = acc[15] * corr + e * v3.w;
        m = mnew;
    }

    #pragma unroll
    for (int off = 1; off <= 2; off <<= 1) {
        float mo = __shfl_xor_sync(0xffffffffu, m, off);
        float lo = __shfl_xor_sync(0xffffffffu, l, off);
        float mm = fmaxf(m, mo);
        float ca = __expf(m  - mm);
        float cb = __expf(mo - mm);
        l = l * ca + lo * cb;
        #pragma unroll
        for (int d = 0; d < HD; d++) {
            float ao = __shfl_xor_sync(0xffffffffu, acc[d], off);
            acc[d] = acc[d] * ca + ao * cb;
        }
        m = mm;
    }

    float inv = 1.f / l;
    float* op = o + (size_t)q * H_DIM + h * HD;
    #pragma unroll
    for (int dd = 0; dd < 4; dd++) {
        int d = lane * 4 + dd;
        op[d] = acc[d] * inv;
    }
}

// ---------------- heads epilogue ----------------
__global__ void final_kernel(float* __restrict__ out) {
    int i = blockIdx.x * blockDim.x + threadIdx.x;
    if (i >= N_TOK) return;
    float bb = 1.f / (1.f + __expf(-g_beta[i]));
    bb = fminf(fmaxf(bb, 1e-6f), 1.f - 1e-6f);
    out[i] = bb;
    float nn = 0.f;
    float lv[LAT_DIM];
    #pragma unroll
    for (int d = 0; d < LAT_DIM; d++) { lv[d] = g_lat[i * LAT_DIM + d]; nn += lv[d] * lv[d]; }
    float inv = 1.f / fmaxf(sqrtf(nn), 1e-12f);
    #pragma unroll
    for (int d = 0; d < LAT_DIM; d++) out[N_TOK + i * LAT_DIM + d] = lv[d] * inv;
}

// ---------------- host orchestration ----------------
extern "C" void kernel_launch(void* const* d_in, const int* in_sizes, int n_in,
                              void* d_out, int out_size) {
    const float* x_raw  = (const float*)d_in[0];
    const float* in_w   = (const float*)d_in[2];
    const float* in_b   = (const float*)d_in[3];
    const float* ln1_s  = (const float*)d_in[4];
    const float* ln1_b  = (const float*)d_in[5];
    const float* qkv_w  = (const float*)d_in[6];
    const float* qkv_b  = (const float*)d_in[7];
    const float* ao_w   = (const float*)d_in[8];
    const float* ao_b   = (const float*)d_in[9];
    const float* ln2_s  = (const float*)d_in[10];
    const float* ln2_b  = (const float*)d_in[11];
    const float* f1_w   = (const float*)d_in[12];
    const float* f1_b   = (const float*)d_in[13];
    const float* f2_w   = (const float*)d_in[14];
    const float* f2_b   = (const float*)d_in[15];
    const float* lat1_w = (const float*)d_in[16];
    const float* lat1_b = (const float*)d_in[17];
    const float* lat2_w = (const float*)d_in[18];
    const float* lat2_b = (const float*)d_in[19];
    const float* b1_w   = (const float*)d_in[20];
    const float* b1_b   = (const float*)d_in[21];
    const float* b2_w   = (const float*)d_in[22];
    const float* b2_b   = (const float*)d_in[23];

    float *x, *xn, *qkv, *attn, *tmp, *lat, *beta;
    cudaGetSymbolAddress((void**)&x,    g_x);
    cudaGetSymbolAddress((void**)&xn,   g_xn);
    cudaGetSymbolAddress((void**)&qkv,  g_qkv);
    cudaGetSymbolAddress((void**)&attn, g_attn);
    cudaGetSymbolAddress((void**)&tmp,  g_tmp);
    cudaGetSymbolAddress((void**)&lat,  g_lat);
    cudaGetSymbolAddress((void**)&beta, g_beta);

    dim3 blk(256);

    nbr_kernel<<<N_TOK / 8, 256>>>(x_raw);

    // input projection: K=16, M=128
    gemm_mma_kernel<<<dim3(N_TOK / GM, H_DIM / GN), blk>>>(
        x_raw, in_w, in_b, nullptr, x, N_TOK, H_DIM, 16, 0);

    for (int l = 0; l < L_LAYER; l++) {
        ln_kernel<<<N_TOK / 8, 256>>>(x, ln1_s + l * H_DIM, ln1_b + l * H_DIM, xn);
        gemm_mma_kernel<<<dim3(N_TOK / GM, (3 * H_DIM) / GN), blk>>>(
            xn, qkv_w + (size_t)l * 3 * H_DIM * H_DIM, qkv_b + l * 3 * H_DIM,
            nullptr, qkv, N_TOK, 3 * H_DIM, H_DIM, 0);
        attn_sparse4_kernel<<<(N_TOK * NH * 4) / 256, 256>>>(qkv, attn);
        gemm_mma_kernel<<<dim3(N_TOK / GM, H_DIM / GN), blk>>>(
            attn, ao_w + (size_t)l * H_DIM * H_DIM, ao_b + l * H_DIM,
            x, x, N_TOK, H_DIM, H_DIM, 0);
        ln_kernel<<<N_TOK / 8, 256>>>(x, ln2_s + l * H_DIM, ln2_b + l * H_DIM, xn);
        gemm_mma_kernel<<<dim3(N_TOK / GM, FF_DIM / GN), blk>>>(
            xn, f1_w + (size_t)l * FF_DIM * H_DIM, f1_b + l * FF_DIM,
            nullptr, tmp, N_TOK, FF_DIM, H_DIM, 1);
        gemm_mma_kernel<<<dim3(N_TOK / GM, H_DIM / GN), blk>>>(
            tmp, f2_w + (size_t)l * H_DIM * FF_DIM, f2_b + l * H_DIM,
            x, x, N_TOK, H_DIM, FF_DIM, 0);
    }

    gemm_mma_kernel<<<dim3(N_TOK / GM, H_DIM / GN), blk>>>(
        x, lat1_w, lat1_b, nullptr, xn, N_TOK, H_DIM, H_DIM, 1);
    gemm_mma_kernel<<<dim3(N_TOK / GM, 1), blk>>>(
        xn, lat2_w, lat2_b, nullptr, lat, N_TOK, LAT_DIM, H_DIM, 0);

    gemm_mma_kernel<<<dim3(N_TOK / GM, 1), blk>>>(
        x, b1_w, b1_b, nullptr, tmp, N_TOK, H_DIM / 2, H_DIM, 1);
    gemm_mma_kernel<<<dim3(N_TOK / GM, 1), blk>>>(
        tmp, b2_w, b2_b, nullptr, beta, N_TOK, 1, H_DIM / 2, 0);

    final_kernel<<<(N_TOK + 255) / 256, 256>>>((float*)d_out);
}

// round 15
// speedup vs baseline: 1.1895x; 1.1895x over previous
#include <cuda_runtime.h>
#include <math.h>

#define N_TOK   4096
#define H_DIM   128
#define NH      8
#define HD      16
#define FF_DIM  256
#define L_LAYER 4
#define LAT_DIM 16
#define CAP     128

// ---------------- scratch (static device globals; no runtime alloc) ----------------
__device__ __align__(256) float g_x   [N_TOK * H_DIM];
__device__ __align__(256) float g_xn  [N_TOK * H_DIM];
__device__ __align__(256) float g_qkv [N_TOK * 3 * H_DIM];
__device__ __align__(256) float g_attn[N_TOK * H_DIM];
__device__ __align__(256) float g_tmp [N_TOK * FF_DIM];
__device__ __align__(256) float g_lat [N_TOK * LAT_DIM];
__device__ __align__(256) float g_beta[N_TOK];
__device__ __align__(256) int   g_nbr [N_TOK * CAP];
__device__ __align__(256) int   g_ncnt[N_TOK];

// ---------------- neighbor list build: eta/phi inline, smem-staged ----------------
__global__ __launch_bounds__(256)
void nbr_kernel(const float* __restrict__ x_raw) {
    __shared__ float se[N_TOK];
    __shared__ float sp[N_TOK];
    const int tid = threadIdx.x;
    #pragma unroll
    for (int t = 0; t < N_TOK / 256; t++) {
        int i = tid + t * 256;
        se[i] = x_raw[i * 16 + 1] * 5.24f   + (-2.62f);
        sp[i] = x_raw[i * 16 + 2] * 6.2832f + (-3.1416f);
    }
    __syncthreads();

    const int lane = tid & 31;
    const int q    = blockIdx.x * 8 + (tid >> 5);
    const float eq = se[q], pq = sp[q];
    int cnt = 0;
    for (int k = lane; k < N_TOK; k += 32) {
        float de = eq - se[k];
        float dp = pq - sp[k];
        dp -= 6.28318530718f * rintf(dp * 0.159154943092f);
        bool hit = (de * de + dp * dp) <= 0.04f;
        unsigned mask = __ballot_sync(0xffffffffu, hit);
        if (hit) {
            int off = cnt + __popc(mask & ((1u << lane) - 1u));
            if (off < CAP) g_nbr[q * CAP + off] = k;
        }
        cnt += __popc(mask);
    }
    if (lane == 0) g_ncnt[q] = min(cnt, CAP);
}

// ---------------- tf32 tensor-core GEMM: 64x64 tile, k32 double-buffered -----------
// C = A(NxK) @ W(MxK)^T + bias (+res)(relu?). 256 threads = 8 warps.
// Warp w: rows (w>>1)*16..+15, cols (w&1)*32..+31 (4 n8 tiles). mma.m16n8k8 tf32.
#define GM 64
#define GN 64
#define GK 32
#define PITCH 36   // 32 + 4 pad: word addr = 4*row + k (mod 32) -> conflict-free frags

__device__ __forceinline__ unsigned f2tf32(float f) {
    unsigned u;
    asm("cvt.rna.tf32.f32 %0, %1;" : "=r"(u) : "f"(f));
    return u;
}

__global__ __launch_bounds__(256)
void gemm_mma_kernel(const float* __restrict__ A, const float* __restrict__ W,
                     const float* __restrict__ bias, const float* __restrict__ res,
                     float* __restrict__ C, int N, int M, int K, int relu) {
    __shared__ __align__(16) unsigned As[2][GM][PITCH];
    __shared__ __align__(16) unsigned Ws[2][GN][PITCH];

    const int tid  = threadIdx.x;
    const int row0 = blockIdx.x * GM;
    const int col0 = blockIdx.y * GN;
    const int wrp  = tid >> 5;
    const int lane = tid & 31;
    const int r0   = (wrp >> 1) * 16;        // warp row base within tile
    const int n0   = (wrp & 1) * 32;         // warp col base within tile

    // staging coords: 2 float4 of A and 2 of W per thread (k-span 8)
    const int sr  = tid >> 2;                 // 0..63
    const int kq8 = (tid & 3) << 3;           // 0,8,16,24

    float4 pa0, pa1, pw0, pw1;
    {
        int ga = row0 + sr, gw = col0 + sr;
        bool v0 = (kq8     < K), v1 = (kq8 + 4 < K);
        pa0 = (ga < N && v0) ? *(const float4*)(A + (size_t)ga * K + kq8)     : make_float4(0,0,0,0);
        pa1 = (ga < N && v1) ? *(const float4*)(A + (size_t)ga * K + kq8 + 4) : make_float4(0,0,0,0);
        pw0 = (gw < M && v0) ? *(const float4*)(W + (size_t)gw * K + kq8)     : make_float4(0,0,0,0);
        pw1 = (gw < M && v1) ? *(const float4*)(W + (size_t)gw * K + kq8 + 4) : make_float4(0,0,0,0);
    }
    As[0][sr][kq8 + 0] = f2tf32(pa0.x); As[0][sr][kq8 + 1] = f2tf32(pa0.y);
    As[0][sr][kq8 + 2] = f2tf32(pa0.z); As[0][sr][kq8 + 3] = f2tf32(pa0.w);
    As[0][sr][kq8 + 4] = f2tf32(pa1.x); As[0][sr][kq8 + 5] = f2tf32(pa1.y);
    As[0][sr][kq8 + 6] = f2tf32(pa1.z); As[0][sr][kq8 + 7] = f2tf32(pa1.w);
    Ws[0][sr][kq8 + 0] = f2tf32(pw0.x); Ws[0][sr][kq8 + 1] = f2tf32(pw0.y);
    Ws[0][sr][kq8 + 2] = f2tf32(pw0.z); Ws[0][sr][kq8 + 3] = f2tf32(pw0.w);
    Ws[0][sr][kq8 + 4] = f2tf32(pw1.x); Ws[0][sr][kq8 + 5] = f2tf32(pw1.y);
    Ws[0][sr][kq8 + 6] = f2tf32(pw1.z); Ws[0][sr][kq8 + 7] = f2tf32(pw1.w);
    __syncthreads();

    float c[4][4];   // [n8 tile][c0..c3]
    #pragma unroll
    for (int j = 0; j < 4; j++)
        #pragma unroll
        for (int i = 0; i < 4; i++) c[j][i] = 0.f;

    const int frow = lane >> 2;     // 0..7
    const int fcol = lane & 3;      // 0..3

    const int nk = (K + GK - 1) / GK;
    for (int t = 0; t < nk; t++) {
        int buf = t & 1;
        if (t + 1 < nk) {
            int koff = (t + 1) * GK + kq8;
            int ga = row0 + sr, gw = col0 + sr;
            bool v0 = (koff < K), v1 = (koff + 4 < K);
            pa0 = (ga < N && v0) ? *(const float4*)(A + (size_t)ga * K + koff)     : make_float4(0,0,0,0);
            pa1 = (ga < N && v1) ? *(const float4*)(A + (size_t)ga * K + koff + 4) : make_float4(0,0,0,0);
            pw0 = (gw < M && v0) ? *(const float4*)(W + (size_t)gw * K + koff)     : make_float4(0,0,0,0);
            pw1 = (gw < M && v1) ? *(const float4*)(W + (size_t)gw * K + koff + 4) : make_float4(0,0,0,0);
        }

        #pragma unroll
        for (int kb = 0; kb < GK; kb += 8) {
            unsigned a0 = As[buf][r0 + frow    ][kb + fcol    ];
            unsigned a1 = As[buf][r0 + frow + 8][kb + fcol    ];
            unsigned a2 = As[buf][r0 + frow    ][kb + fcol + 4];
            unsigned a3 = As[buf][r0 + frow + 8][kb + fcol + 4];
            #pragma unroll
            for (int j = 0; j < 4; j++) {
                unsigned b0 = Ws[buf][n0 + j * 8 + frow][kb + fcol    ];
                unsigned b1 = Ws[buf][n0 + j * 8 + frow][kb + fcol + 4];
                asm("mma.sync.aligned.m16n8k8.row.col.f32.tf32.tf32.f32 "
                    "{%0,%1,%2,%3}, {%4,%5,%6,%7}, {%8,%9}, {%0,%1,%2,%3};"
                    : "+f"(c[j][0]), "+f"(c[j][1]), "+f"(c[j][2]), "+f"(c[j][3])
                    : "r"(a0), "r"(a1), "r"(a2), "r"(a3), "r"(b0), "r"(b1));
            }
        }

        if (t + 1 < nk) {
            int nb = buf ^ 1;
            As[nb][sr][kq8 + 0] = f2tf32(pa0.x); As[nb][sr][kq8 + 1] = f2tf32(pa0.y);
            As[nb][sr][kq8 + 2] = f2tf32(pa0.z); As[nb][sr][kq8 + 3] = f2tf32(pa0.w);
            As[nb][sr][kq8 + 4] = f2tf32(pa1.x); As[nb][sr][kq8 + 5] = f2tf32(pa1.y);
            As[nb][sr][kq8 + 6] = f2tf32(pa1.z); As[nb][sr][kq8 + 7] = f2tf32(pa1.w);
            Ws[nb][sr][kq8 + 0] = f2tf32(pw0.x); Ws[nb][sr][kq8 + 1] = f2tf32(pw0.y);
            Ws[nb][sr][kq8 + 2] = f2tf32(pw0.z); Ws[nb][sr][kq8 + 3] = f2tf32(pw0.w);
            Ws[nb][sr][kq8 + 4] = f2tf32(pw1.x); Ws[nb][sr][kq8 + 5] = f2tf32(pw1.y);
            Ws[nb][sr][kq8 + 6] = f2tf32(pw1.z); Ws[nb][sr][kq8 + 7] = f2tf32(pw1.w);
            __syncthreads();
        }
    }

    // epilogue: c[j][0,1] -> row r0+frow, cols 2*fcol(+1); c[j][2,3] -> row+8
    #pragma unroll
    for (int j = 0; j < 4; j++) {
        int gmBase = col0 + n0 + j * 8 + fcol * 2;
        #pragma unroll
        for (int half = 0; half < 2; half++) {
            int gr = row0 + r0 + frow + half * 8;
            if (gr >= N) continue;
            #pragma unroll
            for (int cc = 0; cc < 2; cc++) {
                int gm = gmBase + cc;
                if (gm >= M) continue;
                float v = c[j][half * 2 + cc] + bias[gm];
                if (res)  v += res[(size_t)gr * M + gm];
                if (relu) v = fmaxf(v, 0.f);
                C[(size_t)gr * M + gm] = v;
            }
        }
    }
}

// ---------------- LayerNorm: one warp per row, 8 rows per 256-thread block ---------
__global__ __launch_bounds__(256)
void ln_kernel(const float* __restrict__ x, const float* __restrict__ sc,
               const float* __restrict__ bi, float* __restrict__ out) {
    const int row  = blockIdx.x * 8 + (threadIdx.x >> 5);
    const int lane = threadIdx.x & 31;

    float4 v = *(const float4*)(x + (size_t)row * H_DIM + lane * 4);
    float s  = v.x + v.y + v.z + v.w;
    float s2 = v.x * v.x + v.y * v.y + v.z * v.z + v.w * v.w;
    #pragma unroll
    for (int o = 16; o; o >>= 1) {
        s  += __shfl_xor_sync(0xffffffffu, s,  o);
        s2 += __shfl_xor_sync(0xffffffffu, s2, o);
    }
    float mean = s * (1.f / 128.f);
    float var  = s2 * (1.f / 128.f) - mean * mean;
    float inv  = rsqrtf(var + 1e-5f);

    float4 sc4 = *(const float4*)(sc + lane * 4);
    float4 bi4 = *(const float4*)(bi + lane * 4);
    float4 o4;
    o4.x = (v.x - mean) * inv * sc4.x + bi4.x;
    o4.y = (v.y - mean) * inv * sc4.y + bi4.y;
    o4.z = (v.z - mean) * inv * sc4.z + bi4.z;
    o4.w = (v.w - mean) * inv * sc4.w + bi4.w;
    *(float4*)(out + (size_t)row * H_DIM + lane * 4) = o4;
}

// ---------------- sparse attention: 4 lanes per (query, head) ----------------
__global__ __launch_bounds__(256)
void attn_sparse4_kernel(const float* __restrict__ qkv, float* __restrict__ o) {
    int gid  = blockIdx.x * 256 + threadIdx.x;
    int grp  = gid >> 2;
    int lane = gid & 3;
    int q = grp >> 3;
    int h = grp & 7;

    const float* qp = qkv + (size_t)q * 384 + h * HD;
    float4 q0 = *(const float4*)(qp);
    float4 q1 = *(const float4*)(qp + 4);
    float4 q2 = *(const float4*)(qp + 8);
    float4 q3 = *(const float4*)(qp + 12);

    int cnt = g_ncnt[q];
    const int* nb = &g_nbr[q * CAP];

    float m = -1e30f, l = 0.f;
    float acc[HD];
    #pragma unroll
    for (int d = 0; d < HD; d++) acc[d] = 0.f;

    for (int j = lane; j < cnt; j += 4) {
        int kidx = nb[j];
        const float* kp = qkv + (size_t)kidx * 384 + 128 + h * HD;
        float4 k0 = *(const float4*)(kp);
        float4 k1 = *(const float4*)(kp + 4);
        float4 k2 = *(const float4*)(kp + 8);
        float4 k3 = *(const float4*)(kp + 12);
        float s = q0.x * k0.x + q0.y * k0.y + q0.z * k0.z + q0.w * k0.w
                + q1.x * k1.x + q1.y * k1.y + q1.z * k1.z + q1.w * k1.w
                + q2.x * k2.x + q2.y * k2.y + q2.z * k2.z + q2.w * k2.w
                + q3.x * k3.x + q3.y * k3.y + q3.z * k3.z + q3.w * k3.w;
        s *= 0.25f;
        float mnew = fmaxf(m, s);
        float corr = __expf(m - mnew);
        float e    = __expf(s - mnew);
        l = l * corr + e;
        const float* vp = kp + 128;
        float4 v0 = *(const float4*)(vp);
        float4 v1 = *(const float4*)(vp + 4);
        float4 v2 = *(const float4*)(vp + 8);
        float4 v3 = *(const float4*)(vp + 12);
        acc[0]  = acc[0]  * corr + e * v0.x;  acc[1]  = acc[1]  * corr + e * v0.y;
        acc[2]  = acc[2]  * corr + e * v0.z;  acc[3]  = acc[3]  * corr + e * v0.w;
        acc[4]  = acc[4]  * corr + e * v1.x;  acc[5]  = acc[5]  * corr + e * v1.y;
        acc[6]  = acc[6]  * corr + e * v1.z;  acc[7]  = acc[7]  * corr + e * v1.w;
        acc[8]  = acc[8]  * corr + e * v2.x;  acc[9]  = acc[9]  * corr + e * v2.y;
        acc[10] = acc[10] * corr + e * v2.z;  acc[11] = acc[11] * corr + e * v2.w;
        acc[12] = acc[12] * corr + e * v3.x;  acc[13] = acc[13] * corr + e * v3.y;
        acc[14] = acc[14] * corr + e * v3.z;  acc[15] = acc[15] * corr + e * v3.w;
        m = mnew;
    }

    #pragma unroll
    for (int off = 1; off <= 2; off <<= 1) {
        float mo = __shfl_xor_sync(0xffffffffu, m, off);
        float lo = __shfl_xor_sync(0xffffffffu, l, off);
        float mm = fmaxf(m, mo);
        float ca = __expf(m  - mm);
        float cb = __expf(mo - mm);
        l = l * ca + lo * cb;
        #pragma unroll
        for (int d = 0; d < HD; d++) {
            float ao = __shfl_xor_sync(0xffffffffu, acc[d], off);
            acc[d] = acc[d] * ca + ao * cb;
        }
        m = mm;
    }

    float inv = 1.f / l;
    float* op = o + (size_t)q * H_DIM + h * HD;
    #pragma unroll
    for (int dd = 0; dd < 4; dd++) {
        int d = lane * 4 + dd;
        op[d] = acc[d] * inv;
    }
}

// ---------------- heads epilogue ----------------
__global__ void final_kernel(float* __restrict__ out) {
    int i = blockIdx.x * blockDim.x + threadIdx.x;
    if (i >= N_TOK) return;
    float bb = 1.f / (1.f + __expf(-g_beta[i]));
    bb = fminf(fmaxf(bb, 1e-6f), 1.f - 1e-6f);
    out[i] = bb;
    float nn = 0.f;
    float lv[LAT_DIM];
    #pragma unroll
    for (int d = 0; d < LAT_DIM; d++) { lv[d] = g_lat[i * LAT_DIM + d]; nn += lv[d] * lv[d]; }
    float inv = 1.f / fmaxf(sqrtf(nn), 1e-12f);
    #pragma unroll
    for (int d = 0; d < LAT_DIM; d++) out[N_TOK + i * LAT_DIM + d] = lv[d] * inv;
}

// ---------------- host orchestration ----------------
extern "C" void kernel_launch(void* const* d_in, const int* in_sizes, int n_in,
                              void* d_out, int out_size) {
    const float* x_raw  = (const float*)d_in[0];
    const float* in_w   = (const float*)d_in[2];
    const float* in_b   = (const float*)d_in[3];
    const float* ln1_s  = (const float*)d_in[4];
    const float* ln1_b  = (const float*)d_in[5];
    const float* qkv_w  = (const float*)d_in[6];
    const float* qkv_b  = (const float*)d_in[7];
    const float* ao_w   = (const float*)d_in[8];
    const float* ao_b   = (const float*)d_in[9];
    const float* ln2_s  = (const float*)d_in[10];
    const float* ln2_b  = (const float*)d_in[11];
    const float* f1_w   = (const float*)d_in[12];
    const float* f1_b   = (const float*)d_in[13];
    const float* f2_w   = (const float*)d_in[14];
    const float* f2_b   = (const float*)d_in[15];
    const float* lat1_w = (const float*)d_in[16];
    const float* lat1_b = (const float*)d_in[17];
    const float* lat2_w = (const float*)d_in[18];
    const float* lat2_b = (const float*)d_in[19];
    const float* b1_w   = (const float*)d_in[20];
    const float* b1_b   = (const float*)d_in[21];
    const float* b2_w   = (const float*)d_in[22];
    const float* b2_b   = (const float*)d_in[23];

    float *x, *xn, *qkv, *attn, *tmp, *lat, *beta;
    cudaGetSymbolAddress((void**)&x,    g_x);
    cudaGetSymbolAddress((void**)&xn,   g_xn);
    cudaGetSymbolAddress((void**)&qkv,  g_qkv);
    cudaGetSymbolAddress((void**)&attn, g_attn);
    cudaGetSymbolAddress((void**)&tmp,  g_tmp);
    cudaGetSymbolAddress((void**)&lat,  g_lat);
    cudaGetSymbolAddress((void**)&beta, g_beta);

    dim3 blk(256);

    nbr_kernel<<<N_TOK / 8, 256>>>(x_raw);

    // input projection: K=16, M=128
    gemm_mma_kernel<<<dim3(N_TOK / GM, H_DIM / GN), blk>>>(
        x_raw, in_w, in_b, nullptr, x, N_TOK, H_DIM, 16, 0);

    for (int l = 0; l < L_LAYER; l++) {
        ln_kernel<<<N_TOK / 8, 256>>>(x, ln1_s + l * H_DIM, ln1_b + l * H_DIM, xn);
        gemm_mma_kernel<<<dim3(N_TOK / GM, (3 * H_DIM) / GN), blk>>>(
            xn, qkv_w + (size_t)l * 3 * H_DIM * H_DIM, qkv_b + l * 3 * H_DIM,
            nullptr, qkv, N_TOK, 3 * H_DIM, H_DIM, 0);
        attn_sparse4_kernel<<<(N_TOK * NH * 4) / 256, 256>>>(qkv, attn);
        gemm_mma_kernel<<<dim3(N_TOK / GM, H_DIM / GN), blk>>>(
            attn, ao_w + (size_t)l * H_DIM * H_DIM, ao_b + l * H_DIM,
            x, x, N_TOK, H_DIM, H_DIM, 0);
        ln_kernel<<<N_TOK / 8, 256>>>(x, ln2_s + l * H_DIM, ln2_b + l * H_DIM, xn);
        gemm_mma_kernel<<<dim3(N_TOK / GM, FF_DIM / GN), blk>>>(
            xn, f1_w + (size_t)l * FF_DIM * H_DIM, f1_b + l * FF_DIM,
            nullptr, tmp, N_TOK, FF_DIM, H_DIM, 1);
        gemm_mma_kernel<<<dim3(N_TOK / GM, H_DIM / GN), blk>>>(
            tmp, f2_w + (size_t)l * H_DIM * FF_DIM, f2_b + l * H_DIM,
            x, x, N_TOK, H_DIM, FF_DIM, 0);
    }

    gemm_mma_kernel<<<dim3(N_TOK / GM, H_DIM / GN), blk>>>(
        x, lat1_w, lat1_b, nullptr, xn, N_TOK, H_DIM, H_DIM, 1);
    gemm_mma_kernel<<<dim3(N_TOK / GM, 1), blk>>>(
        xn, lat2_w, lat2_b, nullptr, lat, N_TOK, LAT_DIM, H_DIM, 0);

    gemm_mma_kernel<<<dim3(N_TOK / GM, 1), blk>>>(
        x, b1_w, b1_b, nullptr, tmp, N_TOK, H_DIM / 2, H_DIM, 1);
    gemm_mma_kernel<<<dim3(N_TOK / GM, 1), blk>>>(
        tmp, b2_w, b2_b, nullptr, beta, N_TOK, 1, H_DIM / 2, 0);

    final_kernel<<<(N_TOK + 255) / 256, 256>>>((float*)d_out);
}

// round 16
// speedup vs baseline: 1.2182x; 1.0241x over previous
#include <cuda_runtime.h>
#include <math.h>

#define N_TOK   4096
#define H_DIM   128
#define NH      8
#define HD      16
#define FF_DIM  256
#define L_LAYER 4
#define LAT_DIM 16
#define CAP     128

// ---------------- scratch (static device globals; no runtime alloc) ----------------
__device__ __align__(256) float g_x   [N_TOK * H_DIM];
__device__ __align__(256) float g_xn  [N_TOK * H_DIM];
__device__ __align__(256) float g_qkv [N_TOK * 3 * H_DIM];
__device__ __align__(256) float g_attn[N_TOK * H_DIM];
__device__ __align__(256) float g_tmp [N_TOK * FF_DIM];
__device__ __align__(256) float g_eta [N_TOK];
__device__ __align__(256) float g_phi [N_TOK];
__device__ __align__(256) float g_lat [N_TOK * LAT_DIM];
__device__ __align__(256) float g_beta[N_TOK];
__device__ __align__(256) int   g_nbr [N_TOK * CAP];
__device__ __align__(256) int   g_ncnt[N_TOK];

// ---------------- eta/phi precompute (compact arrays, coalesced-ish) ----------------
__global__ void etaphi_kernel(const float* __restrict__ x_raw) {
    int i = blockIdx.x * blockDim.x + threadIdx.x;
    if (i >= N_TOK) return;
    g_eta[i] = x_raw[i * 16 + 1] * 5.24f   + (-2.62f);
    g_phi[i] = x_raw[i * 16 + 2] * 6.2832f + (-3.1416f);
}

// ---------------- neighbor list: one warp per query, smem-staged compact eta/phi ----
__global__ __launch_bounds__(256)
void nbr_kernel() {
    __shared__ float se[N_TOK];
    __shared__ float sp[N_TOK];
    const int tid = threadIdx.x;
    #pragma unroll
    for (int t = 0; t < N_TOK / 256; t++) {
        int i = tid + t * 256;
        se[i] = g_eta[i];
        sp[i] = g_phi[i];
    }
    __syncthreads();

    const int lane = tid & 31;
    const int q    = blockIdx.x * 8 + (tid >> 5);
    const float eq = se[q], pq = sp[q];
    int cnt = 0;
    for (int k = lane; k < N_TOK; k += 32) {
        float de = eq - se[k];
        float dp = pq - sp[k];
        dp -= 6.28318530718f * rintf(dp * 0.159154943092f);
        bool hit = (de * de + dp * dp) <= 0.04f;
        unsigned mask = __ballot_sync(0xffffffffu, hit);
        if (hit) {
            int off = cnt + __popc(mask & ((1u << lane) - 1u));
            if (off < CAP) g_nbr[q * CAP + off] = k;
        }
        cnt += __popc(mask);
    }
    if (lane == 0) g_ncnt[q] = min(cnt, CAP);
}

// ---------------- tf32 tensor-core GEMM: 64x64 tile, k32 double-buffered -----------
// C = A(NxK) @ W(MxK)^T + bias (+res)(relu?). 256 threads = 8 warps.
// Warp w: rows (w>>1)*16..+15, cols (w&1)*32..+31 (4 n8 tiles). mma.m16n8k8 tf32.
#define GM 64
#define GN 64
#define GK 32
#define PITCH 36   // 32 + 4 pad: conflict-free fragment fetches

__device__ __forceinline__ unsigned f2tf32(float f) {
    unsigned u;
    asm("cvt.rna.tf32.f32 %0, %1;" : "=r"(u) : "f"(f));
    return u;
}

__global__ __launch_bounds__(256)
void gemm_mma_kernel(const float* __restrict__ A, const float* __restrict__ W,
                     const float* __restrict__ bias, const float* __restrict__ res,
                     float* __restrict__ C, int N, int M, int K, int relu) {
    __shared__ __align__(16) unsigned As[2][GM][PITCH];
    __shared__ __align__(16) unsigned Ws[2][GN][PITCH];

    const int tid  = threadIdx.x;
    const int row0 = blockIdx.x * GM;
    const int col0 = blockIdx.y * GN;
    const int wrp  = tid >> 5;
    const int lane = tid & 31;
    const int r0   = (wrp >> 1) * 16;
    const int n0   = (wrp & 1) * 32;

    const int sr  = tid >> 2;                 // 0..63
    const int kq8 = (tid & 3) << 3;           // 0,8,16,24

    float4 pa0, pa1, pw0, pw1;
    {
        int ga = row0 + sr, gw = col0 + sr;
        bool v0 = (kq8     < K), v1 = (kq8 + 4 < K);
        pa0 = (ga < N && v0) ? *(const float4*)(A + (size_t)ga * K + kq8)     : make_float4(0,0,0,0);
        pa1 = (ga < N && v1) ? *(const float4*)(A + (size_t)ga * K + kq8 + 4) : make_float4(0,0,0,0);
        pw0 = (gw < M && v0) ? *(const float4*)(W + (size_t)gw * K + kq8)     : make_float4(0,0,0,0);
        pw1 = (gw < M && v1) ? *(const float4*)(W + (size_t)gw * K + kq8 + 4) : make_float4(0,0,0,0);
    }
    As[0][sr][kq8 + 0] = f2tf32(pa0.x); As[0][sr][kq8 + 1] = f2tf32(pa0.y);
    As[0][sr][kq8 + 2] = f2tf32(pa0.z); As[0][sr][kq8 + 3] = f2tf32(pa0.w);
    As[0][sr][kq8 + 4] = f2tf32(pa1.x); As[0][sr][kq8 + 5] = f2tf32(pa1.y);
    As[0][sr][kq8 + 6] = f2tf32(pa1.z); As[0][sr][kq8 + 7] = f2tf32(pa1.w);
    Ws[0][sr][kq8 + 0] = f2tf32(pw0.x); Ws[0][sr][kq8 + 1] = f2tf32(pw0.y);
    Ws[0][sr][kq8 + 2] = f2tf32(pw0.z); Ws[0][sr][kq8 + 3] = f2tf32(pw0.w);
    Ws[0][sr][kq8 + 4] = f2tf32(pw1.x); Ws[0][sr][kq8 + 5] = f2tf32(pw1.y);
    Ws[0][sr][kq8 + 6] = f2tf32(pw1.z); Ws[0][sr][kq8 + 7] = f2tf32(pw1.w);
    __syncthreads();

    float c[4][4];
    #pragma unroll
    for (int j = 0; j < 4; j++)
        #pragma unroll
        for (int i = 0; i < 4; i++) c[j][i] = 0.f;

    const int frow = lane >> 2;
    const int fcol = lane & 3;

    const int nk = (K + GK - 1) / GK;
    for (int t = 0; t < nk; t++) {
        int buf = t & 1;
        if (t + 1 < nk) {
            int koff = (t + 1) * GK + kq8;
            int ga = row0 + sr, gw = col0 + sr;
            bool v0 = (koff < K), v1 = (koff + 4 < K);
            pa0 = (ga < N && v0) ? *(const float4*)(A + (size_t)ga * K + koff)     : make_float4(0,0,0,0);
            pa1 = (ga < N && v1) ? *(const float4*)(A + (size_t)ga * K + koff + 4) : make_float4(0,0,0,0);
            pw0 = (gw < M && v0) ? *(const float4*)(W + (size_t)gw * K + koff)     : make_float4(0,0,0,0);
            pw1 = (gw < M && v1) ? *(const float4*)(W + (size_t)gw * K + koff + 4) : make_float4(0,0,0,0);
        }

        #pragma unroll
        for (int kb = 0; kb < GK; kb += 8) {
            unsigned a0 = As[buf][r0 + frow    ][kb + fcol    ];
            unsigned a1 = As[buf][r0 + frow + 8][kb + fcol    ];
            unsigned a2 = As[buf][r0 + frow    ][kb + fcol + 4];
            unsigned a3 = As[buf][r0 + frow + 8][kb + fcol + 4];
            #pragma unroll
            for (int j = 0; j < 4; j++) {
                unsigned b0 = Ws[buf][n0 + j * 8 + frow][kb + fcol    ];
                unsigned b1 = Ws[buf][n0 + j * 8 + frow][kb + fcol + 4];
                asm("mma.sync.aligned.m16n8k8.row.col.f32.tf32.tf32.f32 "
                    "{%0,%1,%2,%3}, {%4,%5,%6,%7}, {%8,%9}, {%0,%1,%2,%3};"
                    : "+f"(c[j][0]), "+f"(c[j][1]), "+f"(c[j][2]), "+f"(c[j][3])
                    : "r"(a0), "r"(a1), "r"(a2), "r"(a3), "r"(b0), "r"(b1));
            }
        }

        if (t + 1 < nk) {
            int nb = buf ^ 1;
            As[nb][sr][kq8 + 0] = f2tf32(pa0.x); As[nb][sr][kq8 + 1] = f2tf32(pa0.y);
            As[nb][sr][kq8 + 2] = f2tf32(pa0.z); As[nb][sr][kq8 + 3] = f2tf32(pa0.w);
            As[nb][sr][kq8 + 4] = f2tf32(pa1.x); As[nb][sr][kq8 + 5] = f2tf32(pa1.y);
            As[nb][sr][kq8 + 6] = f2tf32(pa1.z); As[nb][sr][kq8 + 7] = f2tf32(pa1.w);
            Ws[nb][sr][kq8 + 0] = f2tf32(pw0.x); Ws[nb][sr][kq8 + 1] = f2tf32(pw0.y);
            Ws[nb][sr][kq8 + 2] = f2tf32(pw0.z); Ws[nb][sr][kq8 + 3] = f2tf32(pw0.w);
            Ws[nb][sr][kq8 + 4] = f2tf32(pw1.x); Ws[nb][sr][kq8 + 5] = f2tf32(pw1.y);
            Ws[nb][sr][kq8 + 6] = f2tf32(pw1.z); Ws[nb][sr][kq8 + 7] = f2tf32(pw1.w);
            __syncthreads();
        }
    }

    #pragma unroll
    for (int j = 0; j < 4; j++) {
        int gmBase = col0 + n0 + j * 8 + fcol * 2;
        #pragma unroll
        for (int half = 0; half < 2; half++) {
            int gr = row0 + r0 + frow + half * 8;
            if (gr >= N) continue;
            #pragma unroll
            for (int cc = 0; cc < 2; cc++) {
                int gm = gmBase + cc;
                if (gm >= M) continue;
                float v = c[j][half * 2 + cc] + bias[gm];
                if (res)  v += res[(size_t)gr * M + gm];
                if (relu) v = fmaxf(v, 0.f);
                C[(size_t)gr * M + gm] = v;
            }
        }
    }
}

// ---------------- LayerNorm: one warp per row, 8 rows per 256-thread block ---------
__global__ __launch_bounds__(256)
void ln_kernel(const float* __restrict__ x, const float* __restrict__ sc,
               const float* __restrict__ bi, float* __restrict__ out) {
    const int row  = blockIdx.x * 8 + (threadIdx.x >> 5);
    const int lane = threadIdx.x & 31;

    float4 v = *(const float4*)(x + (size_t)row * H_DIM + lane * 4);
    float s  = v.x + v.y + v.z + v.w;
    float s2 = v.x * v.x + v.y * v.y + v.z * v.z + v.w * v.w;
    #pragma unroll
    for (int o = 16; o; o >>= 1) {
        s  += __shfl_xor_sync(0xffffffffu, s,  o);
        s2 += __shfl_xor_sync(0xffffffffu, s2, o);
    }
    float mean = s * (1.f / 128.f);
    float var  = s2 * (1.f / 128.f) - mean * mean;
    float inv  = rsqrtf(var + 1e-5f);

    float4 sc4 = *(const float4*)(sc + lane * 4);
    float4 bi4 = *(const float4*)(bi + lane * 4);
    float4 o4;
    o4.x = (v.x - mean) * inv * sc4.x + bi4.x;
    o4.y = (v.y - mean) * inv * sc4.y + bi4.y;
    o4.z = (v.z - mean) * inv * sc4.z + bi4.z;
    o4.w = (v.w - mean) * inv * sc4.w + bi4.w;
    *(float4*)(out + (size_t)row * H_DIM + lane * 4) = o4;
}

// ---------------- sparse attention: 4 lanes per (query, head) ----------------
__global__ __launch_bounds__(256)
void attn_sparse4_kernel(const float* __restrict__ qkv, float* __restrict__ o) {
    int gid  = blockIdx.x * 256 + threadIdx.x;
    int grp  = gid >> 2;
    int lane = gid & 3;
    int q = grp >> 3;
    int h = grp & 7;

    const float* qp = qkv + (size_t)q * 384 + h * HD;
    float4 q0 = *(const float4*)(qp);
    float4 q1 = *(const float4*)(qp + 4);
    float4 q2 = *(const float4*)(qp + 8);
    float4 q3 = *(const float4*)(qp + 12);

    int cnt = g_ncnt[q];
    const int* nb = &g_nbr[q * CAP];

    float m = -1e30f, l = 0.f;
    float acc[HD];
    #pragma unroll
    for (int d = 0; d < HD; d++) acc[d] = 0.f;

    for (int j = lane; j < cnt; j += 4) {
        int kidx = nb[j];
        const float* kp = qkv + (size_t)kidx * 384 + 128 + h * HD;
        float4 k0 = *(const float4*)(kp);
        float4 k1 = *(const float4*)(kp + 4);
        float4 k2 = *(const float4*)(kp + 8);
        float4 k3 = *(const float4*)(kp + 12);
        float s = q0.x * k0.x + q0.y * k0.y + q0.z * k0.z + q0.w * k0.w
                + q1.x * k1.x + q1.y * k1.y + q1.z * k1.z + q1.w * k1.w
                + q2.x * k2.x + q2.y * k2.y + q2.z * k2.z + q2.w * k2.w
                + q3.x * k3.x + q3.y * k3.y + q3.z * k3.z + q3.w * k3.w;
        s *= 0.25f;
        float mnew = fmaxf(m, s);
        float corr = __expf(m - mnew);
        float e    = __expf(s - mnew);
        l = l * corr + e;
        const float* vp = kp + 128;
        float4 v0 = *(const float4*)(vp);
        float4 v1 = *(const float4*)(vp + 4);
        float4 v2 = *(const float4*)(vp + 8);
        float4 v3 = *(const float4*)(vp + 12);
        acc[0]  = acc[0]  * corr + e * v0.x;  acc[1]  = acc[1]  * corr + e * v0.y;
        acc[2]  = acc[2]  * corr + e * v0.z;  acc[3]  = acc[3]  * corr + e * v0.w;
        acc[4]  = acc[4]  * corr + e * v1.x;  acc[5]  = acc[5]  * corr + e * v1.y;
        acc[6]  = acc[6]  * corr + e * v1.z;  acc[7]  = acc[7]  * corr + e * v1.w;
        acc[8]  = acc[8]  * corr + e * v2.x;  acc[9]  = acc[9]  * corr + e * v2.y;
        acc[10] = acc[10] * corr + e * v2.z;  acc[11] = acc[11] * corr + e * v2.w;
        acc[12] = acc[12] * corr + e * v3.x;  acc[13] = acc[13] * corr + e * v3.y;
        acc[14] = acc[14] * corr + e * v3.z;  acc[15] = acc[15] * corr + e * v3.w;
        m = mnew;
    }

    #pragma unroll
    for (int off = 1; off <= 2; off <<= 1) {
        float mo = __shfl_xor_sync(0xffffffffu, m, off);
        float lo = __shfl_xor_sync(0xffffffffu, l, off);
        float mm = fmaxf(m, mo);
        float ca = __expf(m  - mm);
        float cb = __expf(mo - mm);
        l = l * ca + lo * cb;
        #pragma unroll
        for (int d = 0; d < HD; d++) {
            float ao = __shfl_xor_sync(0xffffffffu, acc[d], off);
            acc[d] = acc[d] * ca + ao * cb;
        }
        m = mm;
    }

    float inv = 1.f / l;
    float* op = o + (size_t)q * H_DIM + h * HD;
    #pragma unroll
    for (int dd = 0; dd < 4; dd++) {
        int d = lane * 4 + dd;
        op[d] = acc[d] * inv;
    }
}

// ---------------- heads epilogue ----------------
__global__ void final_kernel(float* __restrict__ out) {
    int i = blockIdx.x * blockDim.x + threadIdx.x;
    if (i >= N_TOK) return;
    float bb = 1.f / (1.f + __expf(-g_beta[i]));
    bb = fminf(fmaxf(bb, 1e-6f), 1.f - 1e-6f);
    out[i] = bb;
    float nn = 0.f;
    float lv[LAT_DIM];
    #pragma unroll
    for (int d = 0; d < LAT_DIM; d++) { lv[d] = g_lat[i * LAT_DIM + d]; nn += lv[d] * lv[d]; }
    float inv = 1.f / fmaxf(sqrtf(nn), 1e-12f);
    #pragma unroll
    for (int d = 0; d < LAT_DIM; d++) out[N_TOK + i * LAT_DIM + d] = lv[d] * inv;
}

// ---------------- host orchestration ----------------
extern "C" void kernel_launch(void* const* d_in, const int* in_sizes, int n_in,
                              void* d_out, int out_size) {
    const float* x_raw  = (const float*)d_in[0];
    const float* in_w   = (const float*)d_in[2];
    const float* in_b   = (const float*)d_in[3];
    const float* ln1_s  = (const float*)d_in[4];
    const float* ln1_b  = (const float*)d_in[5];
    const float* qkv_w  = (const float*)d_in[6];
    const float* qkv_b  = (const float*)d_in[7];
    const float* ao_w   = (const float*)d_in[8];
    const float* ao_b   = (const float*)d_in[9];
    const float* ln2_s  = (const float*)d_in[10];
    const float* ln2_b  = (const float*)d_in[11];
    const float* f1_w   = (const float*)d_in[12];
    const float* f1_b   = (const float*)d_in[13];
    const float* f2_w   = (const float*)d_in[14];
    const float* f2_b   = (const float*)d_in[15];
    const float* lat1_w = (const float*)d_in[16];
    const float* lat1_b = (const float*)d_in[17];
    const float* lat2_w = (const float*)d_in[18];
    const float* lat2_b = (const float*)d_in[19];
    const float* b1_w   = (const float*)d_in[20];
    const float* b1_b   = (const float*)d_in[21];
    const float* b2_w   = (const float*)d_in[22];
    const float* b2_b   = (const float*)d_in[23];

    float *x, *xn, *qkv, *attn, *tmp, *lat, *beta;
    cudaGetSymbolAddress((void**)&x,    g_x);
    cudaGetSymbolAddress((void**)&xn,   g_xn);
    cudaGetSymbolAddress((void**)&qkv,  g_qkv);
    cudaGetSymbolAddress((void**)&attn, g_attn);
    cudaGetSymbolAddress((void**)&tmp,  g_tmp);
    cudaGetSymbolAddress((void**)&lat,  g_lat);
    cudaGetSymbolAddress((void**)&beta, g_beta);

    dim3 blk(256);

    etaphi_kernel<<<(N_TOK + 255) / 256, 256>>>(x_raw);
    nbr_kernel<<<N_TOK / 8, 256>>>();

    // input projection: K=16, M=128
    gemm_mma_kernel<<<dim3(N_TOK / GM, H_DIM / GN), blk>>>(
        x_raw, in_w, in_b, nullptr, x, N_TOK, H_DIM, 16, 0);

    for (int l = 0; l < L_LAYER; l++) {
        ln_kernel<<<N_TOK / 8, 256>>>(x, ln1_s + l * H_DIM, ln1_b + l * H_DIM, xn);
        gemm_mma_kernel<<<dim3(N_TOK / GM, (3 * H_DIM) / GN), blk>>>(
            xn, qkv_w + (size_t)l * 3 * H_DIM * H_DIM, qkv_b + l * 3 * H_DIM,
            nullptr, qkv, N_TOK, 3 * H_DIM, H_DIM, 0);
        attn_sparse4_kernel<<<(N_TOK * NH * 4) / 256, 256>>>(qkv, attn);
        gemm_mma_kernel<<<dim3(N_TOK / GM, H_DIM / GN), blk>>>(
            attn, ao_w + (size_t)l * H_DIM * H_DIM, ao_b + l * H_DIM,
            x, x, N_TOK, H_DIM, H_DIM, 0);
        ln_kernel<<<N_TOK / 8, 256>>>(x, ln2_s + l * H_DIM, ln2_b + l * H_DIM, xn);
        gemm_mma_kernel<<<dim3(N_TOK / GM, FF_DIM / GN), blk>>>(
            xn, f1_w + (size_t)l * FF_DIM * H_DIM, f1_b + l * FF_DIM,
            nullptr, tmp, N_TOK, FF_DIM, H_DIM, 1);
        gemm_mma_kernel<<<dim3(N_TOK / GM, H_DIM / GN), blk>>>(
            tmp, f2_w + (size_t)l * H_DIM * FF_DIM, f2_b + l * H_DIM,
            x, x, N_TOK, H_DIM, FF_DIM, 0);
    }

    gemm_mma_kernel<<<dim3(N_TOK / GM, H_DIM / GN), blk>>>(
        x, lat1_w, lat1_b, nullptr, xn, N_TOK, H_DIM, H_DIM, 1);
    gemm_mma_kernel<<<dim3(N_TOK / GM, 1), blk>>>(
        xn, lat2_w, lat2_b, nullptr, lat, N_TOK, LAT_DIM, H_DIM, 0);

    gemm_mma_kernel<<<dim3(N_TOK / GM, 1), blk>>>(
        x, b1_w, b1_b, nullptr, tmp, N_TOK, H_DIM / 2, H_DIM, 1);
    gemm_mma_kernel<<<dim3(N_TOK / GM, 1), blk>>>(
        tmp, b2_w, b2_b, nullptr, beta, N_TOK, 1, H_DIM / 2, 0);

    final_kernel<<<(N_TOK + 255) / 256, 256>>>((float*)d_out);
}